// round 3
// baseline (speedup 1.0000x reference)
#include <cuda_runtime.h>
#include <cuda_bf16.h>
#include <cstdint>

// ---------------- problem constants ----------------
#define B_SZ     2048
#define D_SZ     128
#define C_SZ     64
#define T_STEPS  300
#define H1       200
#define HU       100
#define HP       128
#define ROWS_TOTAL (B_SZ * T_STEPS)
#define NUM_TILES  (ROWS_TOTAL / 128)     // 4800
#define MAIN_CTAS  296                    // 2 per SM
#define MAIN_THREADS 256

// fp8-packed-in-b16 layouts (all sizes in b16 units)
#define A_LD   72                          // 64 b16 (=128 fp8 k) + 8 pad
#define B_LD   136                         // 128 b16 n-cols + 8 pad
#define B_TILE (64 * B_LD)                 // 8704 b16 per weight tile
#define SMEM_MAIN (3 * B_TILE * 2 + 2 * 128 * A_LD * 2 + 1024)

// ---------------- device scratch ----------------
__device__ float g_h1[B_SZ * H1];
__device__ float g_h2[B_SZ * H1];
__device__ float g_h [B_SZ * C_SZ];
__device__ float g_P [B_SZ * HP];
__device__ float g_Q [B_SZ * HP];
__device__ uint16_t g_Ub[3 * B_TILE];      // U2^T,U3^T,U4^T as fp8-pair b16, [k2][n]
__device__ float g_c2p[HP], g_c3p[HP], g_c4p[HP];
__device__ float g_F[B_SZ];

// ---------------- helpers ----------------
__device__ __forceinline__ uint32_t smem_u32(const void* p) {
    return (uint32_t)__cvta_generic_to_shared(p);
}
__device__ __forceinline__ uint16_t pack_e4m3x2(float lo, float hi) {
    uint16_t r;
    asm("cvt.rn.satfinite.e4m3x2.f32 %0, %1, %2;" : "=h"(r) : "f"(hi), "f"(lo));
    return r;
}
__device__ __forceinline__ void ldm_x4(uint32_t addr, uint32_t& r0, uint32_t& r1,
                                       uint32_t& r2, uint32_t& r3) {
    asm volatile("ldmatrix.sync.aligned.m8n8.x4.shared.b16 {%0,%1,%2,%3}, [%4];"
                 : "=r"(r0), "=r"(r1), "=r"(r2), "=r"(r3) : "r"(addr));
}
__device__ __forceinline__ void ldm_x4_t(uint32_t addr, uint32_t& r0, uint32_t& r1,
                                         uint32_t& r2, uint32_t& r3) {
    asm volatile("ldmatrix.sync.aligned.m8n8.x4.trans.shared.b16 {%0,%1,%2,%3}, [%4];"
                 : "=r"(r0), "=r"(r1), "=r"(r2), "=r"(r3) : "r"(addr));
}
__device__ __forceinline__ void mma_fp8(float c[4], uint32_t a0, uint32_t a1, uint32_t a2,
                                        uint32_t a3, uint32_t b0, uint32_t b1) {
    asm volatile(
        "mma.sync.aligned.m16n8k32.row.col.f32.e4m3.e4m3.f32 "
        "{%0,%1,%2,%3},{%4,%5,%6,%7},{%8,%9},{%0,%1,%2,%3};"
        : "+f"(c[0]), "+f"(c[1]), "+f"(c[2]), "+f"(c[3])
        : "r"(a0), "r"(a1), "r"(a2), "r"(a3), "r"(b0), "r"(b1));
}

// Warp-tiled 128x128x128(fp8) GEMM from smem.
// A: [128 rows][A_LD] b16 (fp8 pairs along k). W: [64 k2][B_LD] b16 (fp8 pairs along k).
// Warp layout: 4 m-warps x 2 n-warps, warp tile 32x64.
__device__ __forceinline__ void gemm128_fp8(const uint16_t* inS, const uint16_t* wS,
                                            int mw, int nw, int lane, float acc[2][8][4])
{
    #pragma unroll
    for (int mt = 0; mt < 2; mt++)
        #pragma unroll
        for (int nt = 0; nt < 8; nt++)
            #pragma unroll
            for (int i = 0; i < 4; i++) acc[mt][nt][i] = 0.f;

    int l16 = lane & 15, lh = lane >> 4;
    #pragma unroll
    for (int kk = 0; kk < 4; kk++) {       // 4 k-steps of k32 fp8 (16 b16 each)
        int ks = kk * 16;
        uint32_t a[2][4];
        #pragma unroll
        for (int mt = 0; mt < 2; mt++) {
            const uint16_t* p = inS + (mw * 32 + mt * 16 + l16) * A_LD + ks + 8 * lh;
            ldm_x4(smem_u32(p), a[mt][0], a[mt][1], a[mt][2], a[mt][3]);
        }
        uint32_t b[8][2];
        #pragma unroll
        for (int np = 0; np < 4; np++) {
            const uint16_t* p = wS + (ks + l16) * B_LD + nw * 64 + np * 16 + 8 * lh;
            uint32_t r0, r1, r2, r3;
            ldm_x4_t(smem_u32(p), r0, r1, r2, r3);
            b[np * 2][0] = r0;     b[np * 2][1] = r1;
            b[np * 2 + 1][0] = r2; b[np * 2 + 1][1] = r3;
        }
        #pragma unroll
        for (int mt = 0; mt < 2; mt++)
            #pragma unroll
            for (int nt = 0; nt < 8; nt++)
                mma_fp8(acc[mt][nt], a[mt][0], a[mt][1], a[mt][2], a[mt][3],
                        b[nt][0], b[nt][1]);
    }
}

// epilogue: A' = fp8(relu(D + bias)) into outS (b16-pair layout)
__device__ __forceinline__ void epi_relu_store(float acc[2][8][4], const float* biasS,
                                               uint16_t* outS, int mw, int nw, int lane)
{
    int qrow = lane >> 2, qcol = (lane & 3) * 2;
    #pragma unroll
    for (int mt = 0; mt < 2; mt++) {
        int r = mw * 32 + mt * 16 + qrow;
        #pragma unroll
        for (int nt = 0; nt < 8; nt++) {
            int c = nw * 64 + nt * 8 + qcol;           // even
            float b0 = biasS[c], b1 = biasS[c + 1];
            float v0 = fmaxf(acc[mt][nt][0] + b0, 0.f);
            float v1 = fmaxf(acc[mt][nt][1] + b1, 0.f);
            float v2 = fmaxf(acc[mt][nt][2] + b0, 0.f);
            float v3 = fmaxf(acc[mt][nt][3] + b1, 0.f);
            outS[r * A_LD + (c >> 1)]       = pack_e4m3x2(v0, v1);
            outS[(r + 8) * A_LD + (c >> 1)] = pack_e4m3x2(v2, v3);
        }
    }
}

// ---------------- prep: small SIMT GEMM, 32x64 tiles ----------------
__global__ void gemm_kernel(const float* __restrict__ A, int lda,
                            const float* __restrict__ W, int ldw,
                            const float* __restrict__ bias,
                            float* __restrict__ C, int ldc,
                            int M, int N, int K, int Nstore, int act)
{
    __shared__ float As[16][33];
    __shared__ float Ws[16][68];
    int tid = threadIdx.x;
    int tx = tid & 15, ty = tid >> 4;
    int m0 = blockIdx.y * 32, n0 = blockIdx.x * 64;
    float acc[2][4] = {};
    int ktiles = (K + 15) >> 4;
    for (int kt = 0; kt < ktiles; kt++) {
        int k0 = kt * 16;
        #pragma unroll
        for (int it = 0; it < 2; it++) {
            int e = tid + it * 256;
            int r = e >> 4, k = e & 15;
            As[k][r] = (m0 + r < M && k0 + k < K) ? A[(m0 + r) * lda + k0 + k] : 0.f;
        }
        #pragma unroll
        for (int it = 0; it < 4; it++) {
            int e = tid + it * 256;
            int k = e >> 6, c = e & 63;
            Ws[k][c] = (k0 + k < K && n0 + c < N) ? W[(k0 + k) * ldw + n0 + c] : 0.f;
        }
        __syncthreads();
        #pragma unroll
        for (int k = 0; k < 16; k++) {
            float a0 = As[k][ty * 2], a1 = As[k][ty * 2 + 1];
            float4 w = *(const float4*)&Ws[k][tx * 4];
            acc[0][0] += a0 * w.x; acc[0][1] += a0 * w.y;
            acc[0][2] += a0 * w.z; acc[0][3] += a0 * w.w;
            acc[1][0] += a1 * w.x; acc[1][1] += a1 * w.y;
            acc[1][2] += a1 * w.z; acc[1][3] += a1 * w.w;
        }
        __syncthreads();
    }
    #pragma unroll
    for (int i = 0; i < 2; i++) {
        int r = m0 + ty * 2 + i;
        if (r >= M) continue;
        #pragma unroll
        for (int j = 0; j < 4; j++) {
            int c = n0 + tx * 4 + j;
            if (c >= Nstore) continue;
            float v = 0.f;
            if (c < N) {
                v = acc[i][j] + (bias ? bias[c] : 0.f);
                if (act == 1) v = fmaxf(v, 0.f);
            }
            C[r * ldc + c] = v;
        }
    }
}

// ---------------- pack: weights -> transposed fp8-pair b16 [k2][n] ----------------
__global__ void pack_kernel(const float* __restrict__ U2, const float* __restrict__ U3,
                            const float* __restrict__ U4, const float* __restrict__ c2,
                            const float* __restrict__ c3, const float* __restrict__ c4)
{
    int e = blockIdx.x * blockDim.x + threadIdx.x;   // 0..8191
    int which = blockIdx.y;
    if (which < 3) {
        int k2 = e >> 7, n = e & 127;                // b16 element (k2, n)
        const float* src = which == 0 ? U2 : (which == 1 ? U3 : U4);
        int Nr = (which == 2) ? D_SZ : HU;
        int k0 = 2 * k2, k1 = 2 * k2 + 1;
        float v0 = (k0 < HU && n < Nr) ? src[k0 * Nr + n] : 0.f;
        float v1 = (k1 < HU && n < Nr) ? src[k1 * Nr + n] : 0.f;
        g_Ub[which * B_TILE + k2 * B_LD + n] = pack_e4m3x2(v0, v1);
    } else {
        if (e < HP) {
            g_c2p[e] = e < HU ? c2[e] : 0.f;
            g_c3p[e] = e < HU ? c3[e] : 0.f;
            g_c4p[e] = c4[e];
        }
        if (e < B_SZ) g_F[e] = 0.f;
    }
}

// ---------------- main: persistent fp8 mma kernel ----------------
__global__ void __launch_bounds__(MAIN_THREADS, 2)
umnn_main(const float* __restrict__ x)
{
    extern __shared__ unsigned char smraw[];
    uintptr_t base = ((uintptr_t)smraw + 15) & ~(uintptr_t)15;
    uint16_t* Ws  = (uint16_t*)base;                 // 3 * B_TILE b16
    uint16_t* As1 = Ws + 3 * B_TILE;                 // 128 * A_LD
    uint16_t* As2 = As1 + 128 * A_LD;

    __shared__ float xs[2][128];
    __shared__ float bc2[128], bc3[128], bc4[128];
    __shared__ float sF[2];

    int tid = threadIdx.x;
    int lane = tid & 31, warp = tid >> 5;
    int mw = warp & 3, nw = warp >> 2;

    if (tid < 128) {
        bc2[tid] = g_c2p[tid];
        bc3[tid] = g_c3p[tid];
        bc4[tid] = g_c4p[tid];
    }
    {   // load all 3 weight tiles once (52KB), resident for whole kernel
        const uint4* src = (const uint4*)g_Ub;
        uint4* dst = (uint4*)Ws;
        for (int i = tid; i < 3 * B_TILE / 8; i += MAIN_THREADS) dst[i] = src[i];
    }
    __syncthreads();

    for (int tile = blockIdx.x; tile < NUM_TILES; tile += gridDim.x) {
        int r0 = tile * 128;
        int b0 = r0 / T_STEPS;
        int b1 = (r0 + 127) / T_STEPS;

        if (tid < 128) xs[0][tid] = __ldg(x + b0 * D_SZ + tid);
        else           xs[1][tid - 128] = __ldg(x + b1 * D_SZ + (tid - 128));
        if (tid < 2) sF[tid] = 0.f;

        // ---- build A1 = fp8(relu(t*P[b] + Q[b])) : 2 threads per row ----
        {
            int lr = tid >> 1, half = tid & 1;
            int r = r0 + lr;
            int b = r / T_STEPS;
            int t = r - b * T_STEPS;
            float tv = ((float)t + 0.5f) * (1.0f / T_STEPS);
            const float4* Pp = (const float4*)(g_P + b * HP) + half * 16;
            const float4* Qp = (const float4*)(g_Q + b * HP) + half * 16;
            uint32_t* dst = (uint32_t*)(As1 + lr * A_LD) + half * 16;
            #pragma unroll
            for (int j = 0; j < 16; j++) {
                float4 p = __ldg(Pp + j);
                float4 q = __ldg(Qp + j);
                float v0 = fmaxf(fmaf(tv, p.x, q.x), 0.f);
                float v1 = fmaxf(fmaf(tv, p.y, q.y), 0.f);
                float v2 = fmaxf(fmaf(tv, p.z, q.z), 0.f);
                float v3 = fmaxf(fmaf(tv, p.w, q.w), 0.f);
                uint32_t lo = pack_e4m3x2(v0, v1);
                uint32_t hi = pack_e4m3x2(v2, v3);
                dst[j] = lo | (hi << 16);
            }
        }
        __syncthreads();

        float acc[2][8][4];

        // Layer 2: A2 = relu(A1 @ U2 + c2)
        gemm128_fp8(As1, Ws, mw, nw, lane, acc);
        epi_relu_store(acc, bc2, As2, mw, nw, lane);
        __syncthreads();

        // Layer 3: A3 = relu(A2 @ U3 + c3)
        gemm128_fp8(As2, Ws + B_TILE, mw, nw, lane, acc);
        epi_relu_store(acc, bc3, As1, mw, nw, lane);
        __syncthreads();

        // Layer 4: f = elu(A3 @ U4 + c4) + 1 ; G_row = f . x_b
        gemm128_fp8(As1, Ws + 2 * B_TILE, mw, nw, lane, acc);
        {
            int qrow = lane >> 2, qcol = (lane & 3) * 2;
            #pragma unroll
            for (int mt = 0; mt < 2; mt++) {
                int rA = mw * 32 + mt * 16 + qrow;
                int rB = rA + 8;
                int selA = ((r0 + rA) / T_STEPS) != b0;
                int selB = ((r0 + rB) / T_STEPS) != b0;
                float sA = 0.f, sB = 0.f;
                #pragma unroll
                for (int nt = 0; nt < 8; nt++) {
                    int c = nw * 64 + nt * 8 + qcol;
                    float bv0 = bc4[c], bv1 = bc4[c + 1];
                    float p0 = acc[mt][nt][0] + bv0, p1 = acc[mt][nt][1] + bv1;
                    float p2 = acc[mt][nt][2] + bv0, p3 = acc[mt][nt][3] + bv1;
                    float f0 = p0 > 0.f ? p0 + 1.f : __expf(p0);
                    float f1 = p1 > 0.f ? p1 + 1.f : __expf(p1);
                    float f2 = p2 > 0.f ? p2 + 1.f : __expf(p2);
                    float f3 = p3 > 0.f ? p3 + 1.f : __expf(p3);
                    sA += f0 * xs[selA][c] + f1 * xs[selA][c + 1];
                    sB += f2 * xs[selB][c] + f3 * xs[selB][c + 1];
                }
                sA += __shfl_xor_sync(0xffffffff, sA, 1);
                sA += __shfl_xor_sync(0xffffffff, sA, 2);
                sB += __shfl_xor_sync(0xffffffff, sB, 1);
                sB += __shfl_xor_sync(0xffffffff, sB, 2);
                if ((lane & 3) == 0) {
                    atomicAdd(&sF[selA], sA);
                    atomicAdd(&sF[selB], sB);
                }
            }
        }
        __syncthreads();
        if (tid < 2) {
            int bb = tid == 0 ? b0 : b1;
            if (tid == 0 || b1 != b0) atomicAdd(&g_F[bb], sF[tid]);
        }
        __syncthreads();
    }
}

// ---------------- finish: sigmoid(F / T) ----------------
__global__ void finish_kernel(float* __restrict__ out)
{
    int i = blockIdx.x * blockDim.x + threadIdx.x;
    if (i < B_SZ) {
        float F = g_F[i] * (1.0f / T_STEPS);
        out[i] = 1.0f / (1.0f + expf(-F));
    }
}

// ---------------- launch ----------------
extern "C" void kernel_launch(void* const* d_in, const int* in_sizes, int n_in,
                              void* d_out, int out_size)
{
    (void)in_sizes; (void)n_in; (void)out_size;
    const float* x  = (const float*)d_in[0];
    const float* W1 = (const float*)d_in[1];
    const float* b1 = (const float*)d_in[2];
    const float* W2 = (const float*)d_in[3];
    const float* b2 = (const float*)d_in[4];
    const float* W3 = (const float*)d_in[5];
    const float* b3 = (const float*)d_in[6];
    const float* U1 = (const float*)d_in[7];
    const float* c1 = (const float*)d_in[8];
    const float* U2 = (const float*)d_in[9];
    const float* c2 = (const float*)d_in[10];
    const float* U3 = (const float*)d_in[11];
    const float* c3 = (const float*)d_in[12];
    const float* U4 = (const float*)d_in[13];
    const float* c4 = (const float*)d_in[14];
    float* out = (float*)d_out;

    float *ph1, *ph2, *ph, *pP, *pQ;
    cudaGetSymbolAddress((void**)&ph1, g_h1);
    cudaGetSymbolAddress((void**)&ph2, g_h2);
    cudaGetSymbolAddress((void**)&ph,  g_h);
    cudaGetSymbolAddress((void**)&pP,  g_P);
    cudaGetSymbolAddress((void**)&pQ,  g_Q);

    cudaFuncSetAttribute(umnn_main, cudaFuncAttributeMaxDynamicSharedMemorySize, SMEM_MAIN);

    // weight pack (transpose + fp8-pair b16) + bias pad + zero F
    pack_kernel<<<dim3(32, 4), 256>>>(U2, U3, U4, c2, c3, c4);

    // embedding MLP
    gemm_kernel<<<dim3(4, 64), 256>>>(x,   D_SZ, W1, H1,   b1, ph1, H1,   B_SZ, H1,   D_SZ, H1,   1);
    gemm_kernel<<<dim3(4, 64), 256>>>(ph1, H1,   W2, H1,   b2, ph2, H1,   B_SZ, H1,   H1,   H1,   1);
    gemm_kernel<<<dim3(1, 64), 256>>>(ph2, H1,   W3, C_SZ, b3, ph,  C_SZ, B_SZ, C_SZ, H1,   C_SZ, 1);
    // P = x @ U1[:128,:] ; Q = h @ U1[128:,:] + c1 (both padded to 128 cols)
    gemm_kernel<<<dim3(2, 64), 256>>>(x,  D_SZ, U1,             HU, nullptr, pP, HP, B_SZ, HU, D_SZ, HP, 0);
    gemm_kernel<<<dim3(2, 64), 256>>>(ph, C_SZ, U1 + D_SZ * HU, HU, c1,      pQ, HP, B_SZ, HU, C_SZ, HP, 0);

    // persistent fp8 mma main kernel
    umnn_main<<<MAIN_CTAS, MAIN_THREADS, SMEM_MAIN>>>(x);

    finish_kernel<<<(B_SZ + 255) / 256, 256>>>(out);
}

// round 4
// speedup vs baseline: 1.0934x; 1.0934x over previous
#include <cuda_runtime.h>
#include <cuda_bf16.h>
#include <cstdint>

// ---------------- problem constants ----------------
#define B_SZ     2048
#define D_SZ     128
#define C_SZ     64
#define T_STEPS  300
#define HU       100
#define ROWS_TOTAL (B_SZ * T_STEPS)       // 614400
#define TILE_M   256
#define N_TILES  (ROWS_TOTAL / TILE_M)    // 2400
#define MAIN_CTAS 152
#define MAIN_THREADS 512

#define KP      112                        // padded hidden (7 k-steps of 16)
#define A_LD    120                        // activation row stride (b16), 16B-mult
#define W23_LD  120                        // U2/U3 tile width (n<=112 used)
#define W4_LD   136                        // U4 tile width (n=128)
#define W2_OFF  0
#define W3_OFF  (KP * W23_LD)              // 13440
#define W4_OFF  (2 * KP * W23_LD)          // 26880
#define W_TOTAL (2 * KP * W23_LD + KP * W4_LD)   // 42112 b16
#define SMEM_MAIN (2 * TILE_M * A_LD * 2 + W_TOTAL * 2)   // 207104 B

// ---------------- device scratch ----------------
__device__ float g_h1[B_SZ * 200];
__device__ float g_h2[B_SZ * 200];
__device__ float g_h [B_SZ * C_SZ];
__device__ __align__(16) __nv_bfloat16 g_Pb[B_SZ * KP];   // x @ U1[:128], bf16, 112-wide
__device__ __align__(16) __nv_bfloat16 g_Qb[B_SZ * KP];   // h @ U1[128:] + c1
__device__ __align__(16) uint16_t g_Ub[W_TOTAL];          // U2,U3,U4 padded bf16 [k][n]
__device__ float g_c2p[128], g_c3p[128], g_c4p[128];
__device__ float g_F[B_SZ];

// ---------------- helpers ----------------
__device__ __forceinline__ uint32_t smem_u32(const void* p) {
    return (uint32_t)__cvta_generic_to_shared(p);
}
__device__ __forceinline__ void ldm_x4(uint32_t addr, uint32_t& r0, uint32_t& r1,
                                       uint32_t& r2, uint32_t& r3) {
    asm volatile("ldmatrix.sync.aligned.m8n8.x4.shared.b16 {%0,%1,%2,%3}, [%4];"
                 : "=r"(r0), "=r"(r1), "=r"(r2), "=r"(r3) : "r"(addr));
}
__device__ __forceinline__ void ldm_x4_t(uint32_t addr, uint32_t& r0, uint32_t& r1,
                                         uint32_t& r2, uint32_t& r3) {
    asm volatile("ldmatrix.sync.aligned.m8n8.x4.trans.shared.b16 {%0,%1,%2,%3}, [%4];"
                 : "=r"(r0), "=r"(r1), "=r"(r2), "=r"(r3) : "r"(addr));
}
__device__ __forceinline__ void mma_bf16(float c[4], uint32_t a0, uint32_t a1, uint32_t a2,
                                         uint32_t a3, uint32_t b0, uint32_t b1) {
    asm volatile(
        "mma.sync.aligned.m16n8k16.row.col.f32.bf16.bf16.f32 "
        "{%0,%1,%2,%3},{%4,%5,%6,%7},{%8,%9},{%0,%1,%2,%3};"
        : "+f"(c[0]), "+f"(c[1]), "+f"(c[2]), "+f"(c[3])
        : "r"(a0), "r"(a1), "r"(a2), "r"(a3), "r"(b0), "r"(b1));
}
__device__ __forceinline__ void barpair(int mw) {
    asm volatile("bar.sync %0, 64;" :: "r"(mw + 1) : "memory");
}

// 32-row-stripe x (NT*8*2 cols) x 112 GEMM. A: [TILE_M][A_LD] bf16, warp-pair stripe.
// W: [112][BLD] bf16 [k][n]. 2 n-warps of NT n-tiles each.
template<int NT, int BLD>
__device__ __forceinline__ void gemm_t(const uint16_t* aS, const uint16_t* wS,
                                       int mw, int nw, int lane, float acc[2][8][4])
{
    #pragma unroll
    for (int mt = 0; mt < 2; mt++)
        #pragma unroll
        for (int nt = 0; nt < NT; nt++)
            #pragma unroll
            for (int i = 0; i < 4; i++) acc[mt][nt][i] = 0.f;

    int l16 = lane & 15, lh = lane >> 4;
    #pragma unroll
    for (int kk = 0; kk < 7; kk++) {
        int ks = kk * 16;
        uint32_t a[2][4];
        #pragma unroll
        for (int mt = 0; mt < 2; mt++) {
            const uint16_t* p = aS + (mw * 32 + mt * 16 + l16) * A_LD + ks + 8 * lh;
            ldm_x4(smem_u32(p), a[mt][0], a[mt][1], a[mt][2], a[mt][3]);
        }
        uint32_t b[8][2];
        #pragma unroll
        for (int np = 0; np < 4; np++) {
            const uint16_t* p = wS + (ks + l16) * BLD + nw * (NT * 8) + np * 16 + 8 * lh;
            uint32_t r0, r1, r2, r3;
            ldm_x4_t(smem_u32(p), r0, r1, r2, r3);
            b[np * 2][0] = r0;     b[np * 2][1] = r1;
            b[np * 2 + 1][0] = r2; b[np * 2 + 1][1] = r3;
        }
        #pragma unroll
        for (int mt = 0; mt < 2; mt++)
            #pragma unroll
            for (int nt = 0; nt < NT; nt++)
                mma_bf16(acc[mt][nt], a[mt][0], a[mt][1], a[mt][2], a[mt][3],
                         b[nt][0], b[nt][1]);
    }
}

template<int NT>
__device__ __forceinline__ void epi_relu(float acc[2][8][4], const float* biasS,
                                         uint16_t* outS, int mw, int nw, int lane)
{
    int qrow = lane >> 2, qcol = (lane & 3) * 2;
    #pragma unroll
    for (int mt = 0; mt < 2; mt++) {
        int r = mw * 32 + mt * 16 + qrow;
        #pragma unroll
        for (int nt = 0; nt < NT; nt++) {
            int c = nw * (NT * 8) + nt * 8 + qcol;
            float b0 = biasS[c], b1 = biasS[c + 1];
            float v0 = fmaxf(acc[mt][nt][0] + b0, 0.f);
            float v1 = fmaxf(acc[mt][nt][1] + b1, 0.f);
            float v2 = fmaxf(acc[mt][nt][2] + b0, 0.f);
            float v3 = fmaxf(acc[mt][nt][3] + b1, 0.f);
            __nv_bfloat162 h0 = __floats2bfloat162_rn(v0, v1);
            __nv_bfloat162 h1 = __floats2bfloat162_rn(v2, v3);
            *(uint32_t*)(outS + r * A_LD + c)       = *(uint32_t*)&h0;
            *(uint32_t*)(outS + (r + 8) * A_LD + c) = *(uint32_t*)&h1;
        }
    }
}

// ---------------- prep: whole-K staged SIMT GEMM, 64x64 tiles ----------------
// mode: 1 = fp32 relu store; 2 = bf16 store (no act)
__global__ void gemm_prep(const float* __restrict__ A, int lda,
                          const float* __restrict__ W, int ldw,
                          const float* __restrict__ bias,
                          void* __restrict__ C, int ldc,
                          int M, int N, int K, int Nstore, int mode)
{
    extern __shared__ float sh[];
    float* As = sh;              // [K][68]  (col r)
    float* Ws = sh + K * 68;     // [K][68]  (col c)
    int tid = threadIdx.x;       // 256
    int lane = tid & 31, w = tid >> 5;
    int m0 = blockIdx.y * 64, n0 = blockIdx.x * 64;

    for (int r = w; r < 64; r += 8) {
        const float* src = A + (m0 + r) * lda;
        for (int k = lane; k < K; k += 32) As[k * 68 + r] = src[k];
    }
    for (int k = w; k < K; k += 8) {
        const float* src = W + k * ldw + n0;
        for (int c = lane; c < 64; c += 32)
            Ws[k * 68 + c] = (n0 + c < N) ? src[c] : 0.f;
    }
    __syncthreads();

    int tx = tid & 15, ty = tid >> 4;
    float acc[4][4] = {};
    #pragma unroll 4
    for (int k = 0; k < K; k++) {
        float4 a = *(const float4*)&As[k * 68 + ty * 4];
        float4 wv = *(const float4*)&Ws[k * 68 + tx * 4];
        float av[4] = {a.x, a.y, a.z, a.w};
        float wvv[4] = {wv.x, wv.y, wv.z, wv.w};
        #pragma unroll
        for (int i = 0; i < 4; i++)
            #pragma unroll
            for (int j = 0; j < 4; j++)
                acc[i][j] += av[i] * wvv[j];
    }
    #pragma unroll
    for (int i = 0; i < 4; i++) {
        int r = m0 + ty * 4 + i;
        #pragma unroll
        for (int j = 0; j < 4; j++) {
            int c = n0 + tx * 4 + j;
            if (c >= Nstore) continue;
            float v = 0.f;
            if (c < N) {
                v = acc[i][j] + (bias ? bias[c] : 0.f);
                if (mode == 1) v = fmaxf(v, 0.f);
            }
            if (mode == 2) ((__nv_bfloat16*)C)[r * ldc + c] = __float2bfloat16(v);
            else           ((float*)C)[r * ldc + c] = v;
        }
    }
}

// ---------------- pack: main weights -> padded bf16 [k][n] + biases + zero F -----
__global__ void pack_kernel(const float* __restrict__ U2, const float* __restrict__ U3,
                            const float* __restrict__ U4, const float* __restrict__ c2,
                            const float* __restrict__ c3, const float* __restrict__ c4)
{
    int e = blockIdx.x * blockDim.x + threadIdx.x;
    int which = blockIdx.y;
    if (which < 3) {
        int LD = (which == 2) ? W4_LD : W23_LD;
        int Nr = (which == 2) ? D_SZ : HU;
        if (e < KP * LD) {
            int k = e / LD, n = e - k * LD;
            const float* src = which == 0 ? U2 : (which == 1 ? U3 : U4);
            float v = (k < HU && n < Nr) ? src[k * Nr + n] : 0.f;
            int off = which == 0 ? W2_OFF : (which == 1 ? W3_OFF : W4_OFF);
            __nv_bfloat16 h = __float2bfloat16(v);
            g_Ub[off + e] = *(uint16_t*)&h;
        }
    } else {
        if (e < 128) {
            g_c2p[e] = e < HU ? c2[e] : 0.f;
            g_c3p[e] = e < HU ? c3[e] : 0.f;
            g_c4p[e] = c4[e];
        }
        if (e < B_SZ) g_F[e] = 0.f;
    }
}

// ---------------- main: persistent bf16 mma kernel, 256-row tiles ----------------
__global__ void __launch_bounds__(MAIN_THREADS, 1)
umnn_main(const float* __restrict__ x)
{
    extern __shared__ __align__(16) uint16_t sm[];
    uint16_t* As1 = sm;
    uint16_t* As2 = sm + TILE_M * A_LD;
    uint16_t* Wsm = sm + 2 * TILE_M * A_LD;
    __shared__ float bc2[128], bc3[128], bc4[128];

    int tid = threadIdx.x;
    int lane = tid & 31, w = tid >> 5;
    int mw = w & 7, nw = w >> 3;

    if (tid < 128) {
        bc2[tid] = g_c2p[tid];
        bc3[tid] = g_c3p[tid];
        bc4[tid] = g_c4p[tid];
    }
    {   // stage all weights (84KB) once
        const uint4* src = (const uint4*)g_Ub;
        uint4* dst = (uint4*)Wsm;
        for (int i = tid; i < W_TOTAL / 8; i += MAIN_THREADS) dst[i] = src[i];
    }
    __syncthreads();

    const uint16_t* W2s = Wsm + W2_OFF;
    const uint16_t* W3s = Wsm + W3_OFF;
    const uint16_t* W4s = Wsm + W4_OFF;

    int sl = nw * 32 + lane;                 // 0..63 within warp-pair
    int blr = sl >> 1, bhalf = sl & 1;       // build: row-in-stripe, col half
    int qrow = lane >> 2, qcol = (lane & 3) * 2;

    float acc[2][8][4];

    for (int tile = blockIdx.x; tile < N_TILES; tile += gridDim.x) {
        int r0 = tile * TILE_M;
        int b0 = r0 / T_STEPS;
        int split = (b0 + 1) * T_STEPS - r0;       // tile-rows >= split belong to b0+1

        barpair(mw);   // previous tile's L4 reads of As1 done (pair scope)

        // ---- build A1 = bf16(relu(t*P[b] + Q[b])) into stripe rows of As1 ----
        {
            int row = mw * 32 + blr;
            int r = r0 + row;
            int b = r / T_STEPS;
            float tv = ((float)(r - b * T_STEPS) + 0.5f) * (1.0f / T_STEPS);
            const uint4* Pp = (const uint4*)(g_Pb + b * KP + bhalf * 56);
            const uint4* Qp = (const uint4*)(g_Qb + b * KP + bhalf * 56);
            uint4* dst = (uint4*)(As1 + row * A_LD + bhalf * 56);
            #pragma unroll
            for (int j = 0; j < 7; j++) {
                uint4 pv = __ldg(Pp + j);
                uint4 qv = __ldg(Qp + j);
                uint32_t pw[4] = {pv.x, pv.y, pv.z, pv.w};
                uint32_t qw[4] = {qv.x, qv.y, qv.z, qv.w};
                uint32_t ow[4];
                #pragma unroll
                for (int u = 0; u < 4; u++) {
                    float2 p2 = __bfloat1622float2(*(__nv_bfloat162*)&pw[u]);
                    float2 q2 = __bfloat1622float2(*(__nv_bfloat162*)&qw[u]);
                    float v0 = fmaxf(fmaf(tv, p2.x, q2.x), 0.f);
                    float v1 = fmaxf(fmaf(tv, p2.y, q2.y), 0.f);
                    __nv_bfloat162 h = __floats2bfloat162_rn(v0, v1);
                    ow[u] = *(uint32_t*)&h;
                }
                dst[j] = make_uint4(ow[0], ow[1], ow[2], ow[3]);
            }
        }
        barpair(mw);

        // ---- L2: A2 = relu(A1 @ U2 + c2) ----
        gemm_t<7, W23_LD>(As1, W2s, mw, nw, lane, acc);
        epi_relu<7>(acc, bc2, As2, mw, nw, lane);
        barpair(mw);

        // ---- L3: A3 = relu(A2 @ U3 + c3) ----
        gemm_t<7, W23_LD>(As2, W3s, mw, nw, lane, acc);
        epi_relu<7>(acc, bc3, As1, mw, nw, lane);
        barpair(mw);

        // ---- L4: f = elu(A3 @ U4 + c4) + 1 ; accumulate f . x[b] ----
        gemm_t<8, W4_LD>(As1, W4s, mw, nw, lane, acc);
        {
            #pragma unroll
            for (int mt = 0; mt < 2; mt++) {
                int rA = mw * 32 + mt * 16 + qrow;
                int rB = rA + 8;
                int bA = b0 + (rA >= split);
                int bB = b0 + (rB >= split);
                const float* xA = x + bA * D_SZ;
                const float* xB = x + bB * D_SZ;
                float sA = 0.f, sB = 0.f;
                #pragma unroll
                for (int nt = 0; nt < 8; nt++) {
                    int c = nw * 64 + nt * 8 + qcol;
                    float bv0 = bc4[c], bv1 = bc4[c + 1];
                    float p0 = acc[mt][nt][0] + bv0, p1 = acc[mt][nt][1] + bv1;
                    float p2 = acc[mt][nt][2] + bv0, p3 = acc[mt][nt][3] + bv1;
                    float f0 = p0 > 0.f ? p0 + 1.f : __expf(p0);
                    float f1 = p1 > 0.f ? p1 + 1.f : __expf(p1);
                    float f2 = p2 > 0.f ? p2 + 1.f : __expf(p2);
                    float f3 = p3 > 0.f ? p3 + 1.f : __expf(p3);
                    sA += f0 * __ldg(xA + c) + f1 * __ldg(xA + c + 1);
                    sB += f2 * __ldg(xB + c) + f3 * __ldg(xB + c + 1);
                }
                sA += __shfl_xor_sync(0xffffffff, sA, 1);
                sA += __shfl_xor_sync(0xffffffff, sA, 2);
                sB += __shfl_xor_sync(0xffffffff, sB, 1);
                sB += __shfl_xor_sync(0xffffffff, sB, 2);
                if ((lane & 3) == 0) {
                    atomicAdd(&g_F[bA], sA);
                    atomicAdd(&g_F[bB], sB);
                }
            }
        }
    }
}

// ---------------- finish: sigmoid(F / T) ----------------
__global__ void finish_kernel(float* __restrict__ out)
{
    int i = blockIdx.x * blockDim.x + threadIdx.x;
    if (i < B_SZ) {
        float F = g_F[i] * (1.0f / T_STEPS);
        out[i] = 1.0f / (1.0f + expf(-F));
    }
}

// ---------------- launch ----------------
extern "C" void kernel_launch(void* const* d_in, const int* in_sizes, int n_in,
                              void* d_out, int out_size)
{
    (void)in_sizes; (void)n_in; (void)out_size;
    const float* x  = (const float*)d_in[0];
    const float* W1 = (const float*)d_in[1];
    const float* b1 = (const float*)d_in[2];
    const float* W2 = (const float*)d_in[3];
    const float* b2 = (const float*)d_in[4];
    const float* W3 = (const float*)d_in[5];
    const float* b3 = (const float*)d_in[6];
    const float* U1 = (const float*)d_in[7];
    const float* c1 = (const float*)d_in[8];
    const float* U2 = (const float*)d_in[9];
    const float* c2 = (const float*)d_in[10];
    const float* U3 = (const float*)d_in[11];
    const float* c3 = (const float*)d_in[12];
    const float* U4 = (const float*)d_in[13];
    const float* c4 = (const float*)d_in[14];
    float* out = (float*)d_out;

    float *ph1, *ph2, *ph;
    void *pPb, *pQb;
    cudaGetSymbolAddress((void**)&ph1, g_h1);
    cudaGetSymbolAddress((void**)&ph2, g_h2);
    cudaGetSymbolAddress((void**)&ph,  g_h);
    cudaGetSymbolAddress(&pPb, g_Pb);
    cudaGetSymbolAddress(&pQb, g_Qb);

    cudaFuncSetAttribute(umnn_main, cudaFuncAttributeMaxDynamicSharedMemorySize, SMEM_MAIN);
    cudaFuncSetAttribute(gemm_prep, cudaFuncAttributeMaxDynamicSharedMemorySize, 200 * 544);

    // weight pack + bias pad + zero F
    pack_kernel<<<dim3(60, 4), 256>>>(U2, U3, U4, c2, c3, c4);

    // embedding MLP (fp32, whole-K staged)
    gemm_prep<<<dim3(4, 32), 256, 128 * 544>>>(x,   D_SZ, W1, 200, b1, ph1, 200, B_SZ, 200, 128, 200, 1);
    gemm_prep<<<dim3(4, 32), 256, 200 * 544>>>(ph1, 200,  W2, 200, b2, ph2, 200, B_SZ, 200, 200, 200, 1);
    gemm_prep<<<dim3(1, 32), 256, 200 * 544>>>(ph2, 200,  W3, C_SZ, b3, ph, C_SZ, B_SZ, C_SZ, 200, C_SZ, 1);
    // P = x @ U1[:128] (bf16, 112-wide padded) ; Q = h @ U1[128:] + c1
    gemm_prep<<<dim3(2, 32), 256, 128 * 544>>>(x,  D_SZ, U1,              HU, nullptr, pPb, KP, B_SZ, HU, 128, KP, 2);
    gemm_prep<<<dim3(2, 32), 256,  64 * 544>>>(ph, C_SZ, U1 + D_SZ * HU,  HU, c1,      pQb, KP, B_SZ, HU, C_SZ, KP, 2);

    // persistent bf16 mma main kernel
    umnn_main<<<MAIN_CTAS, MAIN_THREADS, SMEM_MAIN>>>(x);

    finish_kernel<<<(B_SZ + 255) / 256, 256>>>(out);
}